// round 13
// baseline (speedup 1.0000x reference)
#include <cuda_runtime.h>
#include <cuda_fp16.h>
#include <math.h>

#define NB   8
#define ND   768
#define NCH  3
#define NMIX 5
#define H    10
#define NS   10
#define PI2f 6.283185307179586f
#define ZITTERf 1e-4f
#define INV_TEMP 10.0f
#define LOG2E 1.44269504088896341f

#define NJC 16              // j-chunks in feat
#define JC  48              // ND/NJC
#define ITILE 256           // i-range per feat block (2 i per thread)
#define NI_T  3             // ND/ITILE
#define FEAT_BLOCKS (NB * NCH * NI_T * NJC)   // 1152
#define NT2   6             // feat2 i-tiles of 128
#define FEAT2_BLOCKS (NB * NCH * NT2)          // 144
#define BUILD_BLOCKS 372                       // 372*128 = 47616 entries

#define JT  256             // j-tile in out kernel (== blockDim)
#define IT  24              // i-tile in out kernel (ND/IT = 32)
#define OUT_BLOCKS (NB * (ND / JT) * (ND / IT))   // 768

#define TBLP   1984         // half2 pair-entries per (b,c); 3*TBLP*4 = 23808B shared
#define TSCALE 220.0f       // entries per unit |d| (covers |d| <= 9.0)
#define TCLAMP 1982.0f

// cross-kernel scratch (__device__ globals per allocation rules)
__device__ float g_facc[NB * NCH][NJC][NMIX][ND];   // feat partials, coalesced in i
__device__ float g_hpart[NB * NCH][NT2][H];
__device__ float g_w[NB * NCH * NMIX];
__device__ float g_diag[NCH];
__device__ __align__(16) __half2 g_ftab2[NB * NCH][TBLP];
__device__ int g_c0;    // feat main-work completions (target 1152)
__device__ int g_c1;    // feat2 completions (target 144)
__device__ int g_flag;  // weights ready

__device__ __forceinline__ float ex2f_(float x) {
    float y; asm("ex2.approx.f32 %0, %1;" : "=f"(y) : "f"(x)); return y;
}

// ---------------------------------------------------------------------------
// Kernel 1: feat main (all 1152 blocks) -> tail phases on low-indexed blocks:
//   blocks 0..143  : feat2 (layer-1 + i-reduction) after all main work done
//   block  0       : MLP layers 2-5 + Gumbel weights + diag
//   blocks 0..371  : build the half2 pair-packed lookup tables (128 ent each)
// All spinner blocks (0..371) are first-wave resident (1152 <= 1184 slots at
// __launch_bounds__(128,8)) -> no deadlock. Sync words reset by out_kernel.
// ---------------------------------------------------------------------------
__global__ void __launch_bounds__(128, 8) feat_kernel(
    const float* __restrict__ xc, const float* __restrict__ yc,
    const float* __restrict__ mu, const float* __restrict__ inv_std,
    const float* __restrict__ W1, const float* __restrict__ b1,
    const float* __restrict__ likerr, const float* __restrict__ unif,
    const float* __restrict__ W2, const float* __restrict__ b2,
    const float* __restrict__ W3, const float* __restrict__ b3,
    const float* __restrict__ W4, const float* __restrict__ b4,
    const float* __restrict__ W5, const float* __restrict__ b5)
{
    int bid = blockIdx.x;
    int tid = threadIdx.x;

    __shared__ float4 jt[JC][3];                 // 2304 B (feat main)
    __shared__ float sh2[128 * H];               // 5120 B (feat2 reduction)
    __shared__ float sh_h0[NB][NCH * H];         // MLP scratch
    __shared__ float sh_a[NB][H];
    __shared__ float sh_b[NB][H];
    __shared__ float sh_ll[NB][NCH * NMIX];
    __shared__ float sh_sm[NB][NS][NCH][NMIX];

    // ================= main pairwise reduction =================
    {
        int chunk = bid % NJC;
        int r     = bid / NJC;
        int tile  = r % NI_T;
        int bc    = r / NI_T;
        int c     = bc % NCH;
        int b     = bc / NCH;

        float km2[NMIX], pm[NMIX];
#pragma unroll
        for (int m = 0; m < NMIX; m++) {
            float iv = inv_std[m];
            km2[m] = -0.5f * PI2f * PI2f * iv * iv * LOG2E;
            pm[m]  = PI2f * mu[m];
        }

        int j0 = chunk * JC;
        if (tid < JC) {
            float xv = xc[(b * ND + j0 + tid) * NCH + c];
            float yv = yc[(b * ND + j0 + tid) * NCH + c];
            float cy[NMIX], sy[NMIX];
#pragma unroll
            for (int m = 0; m < NMIX; m++) {
                float s, co;
                __sincosf(pm[m] * xv, &s, &co);
                cy[m] = co * yv;
                sy[m] = s * yv;
            }
            jt[tid][0] = make_float4(cy[0], cy[1], cy[2], cy[3]);
            jt[tid][1] = make_float4(cy[4], sy[0], sy[1], sy[2]);
            jt[tid][2] = make_float4(sy[3], sy[4], xv, 0.f);
        }

        int i0 = tile * ITILE + tid;
        int i1 = i0 + 128;
        float xi0 = xc[(b * ND + i0) * NCH + c];
        float xi1 = xc[(b * ND + i1) * NCH + c];

        float A0[NMIX], B0[NMIX], A1[NMIX], B1[NMIX];
#pragma unroll
        for (int m = 0; m < NMIX; m++) { A0[m] = B0[m] = A1[m] = B1[m] = 0.f; }
        __syncthreads();

#pragma unroll 2
        for (int j = 0; j < JC; j++) {
            float4 t0 = jt[j][0];
            float4 t1 = jt[j][1];
            float4 t2 = jt[j][2];
            float cy[NMIX] = {t0.x, t0.y, t0.z, t0.w, t1.x};
            float sy[NMIX] = {t1.y, t1.z, t1.w, t2.x, t2.y};
            float xj = t2.z;
            float d0 = xi0 - xj, d20 = d0 * d0;
            float d1 = xi1 - xj, d21 = d1 * d1;
#pragma unroll
            for (int m = 0; m < NMIX; m++) {
                float e0 = ex2f_(km2[m] * d20);
                float e1 = ex2f_(km2[m] * d21);
                A0[m] = fmaf(e0, cy[m], A0[m]);
                B0[m] = fmaf(e0, sy[m], B0[m]);
                A1[m] = fmaf(e1, cy[m], A1[m]);
                B1[m] = fmaf(e1, sy[m], B1[m]);
            }
        }

#pragma unroll
        for (int m = 0; m < NMIX; m++) {
            float s0, c0, s1, c1;
            __sincosf(pm[m] * xi0, &s0, &c0);
            __sincosf(pm[m] * xi1, &s1, &c1);
            g_facc[bc][chunk][m][i0] = fmaf(c0, A0[m], s0 * B0[m]);
            g_facc[bc][chunk][m][i1] = fmaf(c1, A1[m], s1 * B1[m]);
        }
    }
    __syncthreads();
    if (tid == 0) { __threadfence(); atomicAdd(&g_c0, 1); }

    if (bid >= BUILD_BLOCKS) return;   // high blocks exit, freeing slots

    // ================= phase A: feat2 on blocks 0..143 =================
    if (bid < FEAT2_BLOCKS) {
        if (tid == 0) {
            while (atomicAdd(&g_c0, 0) < FEAT_BLOCKS) { __nanosleep(64); }
            __threadfence();
        }
        __syncthreads();

        int tile = bid % NT2;
        int bc   = bid / NT2;
        int c    = bc % NCH;
        int b    = bc / NCH;
        int i    = tile * 128 + tid;

        float yi = yc[(b * ND + i) * NCH + c];
        float tif[NMIX + 1];
#pragma unroll
        for (int m = 0; m < NMIX; m++) {
            float s = 0.f;
#pragma unroll
            for (int ch = 0; ch < NJC; ch++) s += g_facc[bc][ch][m][i];
            tif[m] = s + ZITTERf * yi;
        }
        tif[NMIX] = yi;

#pragma unroll
        for (int k = 0; k < H; k++) {
            float s = b1[k];
#pragma unroll
            for (int t = 0; t < NMIX + 1; t++) s = fmaf(W1[k * (NMIX + 1) + t], tif[t], s);
            sh2[tid * H + k] = fmaxf(s, 0.f);
        }
        __syncthreads();

        if (tid < H) {
            float s = 0.f;
            for (int t = 0; t < 128; t++) s += sh2[t * H + tid];
            g_hpart[bc][tile][tid] = s;
        }
        __syncthreads();
        if (tid == 0) { __threadfence(); atomicAdd(&g_c1, 1); }
    }

    // ================= phase B: block 0 runs the MLP =================
    if (bid == 0) {
        if (tid == 0) {
            while (atomicAdd(&g_c1, 0) < FEAT2_BLOCKS) { __nanosleep(64); }
            __threadfence();
        }
        __syncthreads();

        if (tid < NB * NCH) {
            int b = tid / NCH, c = tid % NCH;
            for (int k = 0; k < H; k++) {
                float s = 0.f;
#pragma unroll
                for (int tt = 0; tt < NT2; tt++) s += g_hpart[b * NCH + c][tt][k];
                sh_h0[b][c * H + k] = s * (1.0f / ND);
            }
        }
        if (tid < NCH) {
            float l = fminf(fmaxf(likerr[tid], 0.1f), 1.0f);
            g_diag[tid] = ZITTERf + l * l;
        }
        __syncthreads();

        if (tid < NB * H) {                       // layer 2
            int b = tid / H, k = tid % H;
            float s = b2[k];
            for (int u = 0; u < NCH * H; u++) s = fmaf(W2[k * (NCH * H) + u], sh_h0[b][u], s);
            sh_a[b][k] = fmaxf(s, 0.f);
        }
        __syncthreads();
        if (tid < NB * H) {                       // layer 3
            int b = tid / H, k = tid % H;
            float s = b3[k];
            for (int u = 0; u < H; u++) s = fmaf(W3[k * H + u], sh_a[b][u], s);
            sh_b[b][k] = fmaxf(s, 0.f);
        }
        __syncthreads();
        if (tid < NB * H) {                       // layer 4
            int b = tid / H, k = tid % H;
            float s = b4[k];
            for (int u = 0; u < H; u++) s = fmaf(W4[k * H + u], sh_b[b][u], s);
            sh_a[b][k] = fmaxf(s, 0.f);
        }
        __syncthreads();
        if (tid < NB * NCH * NMIX) {              // layer 5 -> logits
            int b = tid / (NCH * NMIX), n = tid % (NCH * NMIX);
            float s = b5[n];
            for (int u = 0; u < H; u++) s = fmaf(W5[n * H + u], sh_a[b][u], s);
            sh_ll[b][n] = s;
        }
        __syncthreads();

        for (int t = tid; t < NB * NS * NCH; t += 128) {   // gumbel softmax
            int b = t / (NS * NCH);
            int rem = t % (NS * NCH);
            int s = rem / NCH, c = rem % NCH;
            float z[NMIX], mx = -1e30f;
#pragma unroll
            for (int m = 0; m < NMIX; m++) {
                float u = unif[((b * NS + s) * NCH + c) * NMIX + m];
                float g = -__logf(-__logf(u + 1e-20f));
                z[m] = (g + sh_ll[b][c * NMIX + m]) * INV_TEMP;
                mx = fmaxf(mx, z[m]);
            }
            float sum = 0.f, e[NMIX];
#pragma unroll
            for (int m = 0; m < NMIX; m++) { e[m] = __expf(z[m] - mx); sum += e[m]; }
            float inv = 1.f / sum;
#pragma unroll
            for (int m = 0; m < NMIX; m++) sh_sm[b][s][c][m] = e[m] * inv;
        }
        __syncthreads();

        if (tid < NB * NCH * NMIX) {              // mean over samples
            int b = tid / (NCH * NMIX);
            int cm = tid % (NCH * NMIX);
            int c = cm / NMIX, m = cm % NMIX;
            float s = 0.f;
#pragma unroll
            for (int ss = 0; ss < NS; ss++) s += sh_sm[b][ss][c][m];
            g_w[(b * NCH + c) * NMIX + m] = s * (1.0f / NS);
        }
        __syncthreads();
        if (tid == 0) { __threadfence(); atomicExch(&g_flag, 1); }
    }

    // ============ phase C: blocks 0..371 build table entries ============
    if (tid == 0) {
        while (atomicAdd(&g_flag, 0) == 0) { __nanosleep(64); }
        __threadfence();
    }
    __syncthreads();

    {
        int idx = bid * 128 + tid;                // 372*128 = 47616 = 24*1984
        int bc  = idx / TBLP;
        int k   = idx % TBLP;
        float d0 = (float)k * (1.0f / TSCALE);
        float d1 = (float)(k + 1) * (1.0f / TSCALE);
        float d20 = d0 * d0, d21 = d1 * d1;
        float a0 = 0.f, a1 = 0.f;
#pragma unroll
        for (int m = 0; m < NMIX; m++) {
            float iv = inv_std[m];
            float a  = -0.5f * PI2f * PI2f * iv * iv * LOG2E;
            float p  = PI2f * mu[m];
            float w  = g_w[bc * NMIX + m];
            a0 = fmaf(w, ex2f_(a * d20) * __cosf(p * d0), a0);
            a1 = fmaf(w, ex2f_(a * d21) * __cosf(p * d1), a1);
        }
        g_ftab2[bc][k] = __floats2half2_rn(a0, a1);
    }
}

// ---------------------------------------------------------------------------
// Kernel 2: pure LUT output — no barriers, table ready at launch.
// half2 pair-packed table: 1 LDS.32 per lookup (1 bank/lane), 23.8KB shared.
// block = (b, j-tile 256, i-tile 24); grid 768 = one full wave at 6 blocks/SM.
// Resets feat sync words (runs last).
// ---------------------------------------------------------------------------
__global__ void __launch_bounds__(256, 6) out_kernel(
    const float* __restrict__ xc, float* __restrict__ out)
{
    int blk = blockIdx.x;
    int tid = threadIdx.x;

    __shared__ __half2 fs2[NCH * TBLP];   // 23808 B
    __shared__ float xish[IT * NCH];

    int itile = blk % (ND / IT);
    int rr_   = blk / (ND / IT);
    int jt    = rr_ % (ND / JT);
    int ob    = rr_ / (ND / JT);
    int ibase = itile * IT;
    int j     = jt * JT + tid;
    float xj0 = xc[((size_t)ob * ND + j) * NCH + 0];
    float xj1 = xc[((size_t)ob * ND + j) * NCH + 1];
    float xj2 = xc[((size_t)ob * ND + j) * NCH + 2];
    if (tid < IT * NCH)
        xish[tid] = xc[((size_t)ob * ND + ibase) * NCH + tid];

    {
        const float4* src = (const float4*)&g_ftab2[ob * NCH][0];
        float4* dst = (float4*)fs2;
        for (int q = tid; q < NCH * TBLP / 4; q += 256) dst[q] = src[q];
    }
    float dg0 = g_diag[0], dg1 = g_diag[1], dg2 = g_diag[2];
    __syncthreads();

    float* o = out + (((size_t)ob * ND + ibase) * ND + j) * NCH;

#pragma unroll 1
    for (int ii = 0; ii < IT; ii += 2) {
        int iA = ibase + ii;
        int iB = iA + 1;
        float tA0 = fminf(fabsf(xish[ii * NCH + 0] - xj0) * TSCALE, TCLAMP);
        float tA1 = fminf(fabsf(xish[ii * NCH + 1] - xj1) * TSCALE, TCLAMP);
        float tA2 = fminf(fabsf(xish[ii * NCH + 2] - xj2) * TSCALE, TCLAMP);
        float tB0 = fminf(fabsf(xish[ii * NCH + 3] - xj0) * TSCALE, TCLAMP);
        float tB1 = fminf(fabsf(xish[ii * NCH + 4] - xj1) * TSCALE, TCLAMP);
        float tB2 = fminf(fabsf(xish[ii * NCH + 5] - xj2) * TSCALE, TCLAMP);
        int kA0 = (int)tA0, kA1 = (int)tA1, kA2 = (int)tA2;
        int kB0 = (int)tB0, kB1 = (int)tB1, kB2 = (int)tB2;
        float2 pA0 = __half22float2(fs2[0 * TBLP + kA0]);
        float2 pA1 = __half22float2(fs2[1 * TBLP + kA1]);
        float2 pA2 = __half22float2(fs2[2 * TBLP + kA2]);
        float2 pB0 = __half22float2(fs2[0 * TBLP + kB0]);
        float2 pB1 = __half22float2(fs2[1 * TBLP + kB1]);
        float2 pB2 = __half22float2(fs2[2 * TBLP + kB2]);
        float fA0 = tA0 - (float)kA0, fA1 = tA1 - (float)kA1, fA2 = tA2 - (float)kA2;
        float fB0 = tB0 - (float)kB0, fB1 = tB1 - (float)kB1, fB2 = tB2 - (float)kB2;
        float rA0 = fmaf(fA0, pA0.y - pA0.x, pA0.x);
        float rA1 = fmaf(fA1, pA1.y - pA1.x, pA1.x);
        float rA2 = fmaf(fA2, pA2.y - pA2.x, pA2.x);
        float rB0 = fmaf(fB0, pB0.y - pB0.x, pB0.x);
        float rB1 = fmaf(fB1, pB1.y - pB1.x, pB1.x);
        float rB2 = fmaf(fB2, pB2.y - pB2.x, pB2.x);
        if (iA == j) { rA0 += dg0; rA1 += dg1; rA2 += dg2; }
        if (iB == j) { rB0 += dg0; rB1 += dg1; rB2 += dg2; }
        o[0] = rA0; o[1] = rA1; o[2] = rA2;
        o += (size_t)ND * NCH;
        o[0] = rB0; o[1] = rB1; o[2] = rB2;
        o += (size_t)ND * NCH;
    }

    // reset sync words for the next graph replay (kernel boundary publishes)
    if (blk == 0 && tid == 0) { g_c0 = 0; g_c1 = 0; g_flag = 0; }
}

extern "C" void kernel_launch(void* const* d_in, const int* in_sizes, int n_in,
                              void* d_out, int out_size)
{
    const float* xc      = (const float*)d_in[0];
    const float* yc      = (const float*)d_in[1];
    const float* mu      = (const float*)d_in[2];
    const float* inv_std = (const float*)d_in[3];
    const float* likerr  = (const float*)d_in[4];
    const float* unif    = (const float*)d_in[5];
    const float* W1 = (const float*)d_in[6];  const float* b1 = (const float*)d_in[7];
    const float* W2 = (const float*)d_in[8];  const float* b2 = (const float*)d_in[9];
    const float* W3 = (const float*)d_in[10]; const float* b3 = (const float*)d_in[11];
    const float* W4 = (const float*)d_in[12]; const float* b4 = (const float*)d_in[13];
    const float* W5 = (const float*)d_in[14]; const float* b5 = (const float*)d_in[15];

    feat_kernel<<<FEAT_BLOCKS, 128>>>(xc, yc, mu, inv_std, W1, b1, likerr, unif,
                                      W2, b2, W3, b3, W4, b4, W5, b5);
    out_kernel<<<OUT_BLOCKS, 256>>>(xc, (float*)d_out);
}

// round 14
// speedup vs baseline: 1.1413x; 1.1413x over previous
#include <cuda_runtime.h>
#include <cuda_fp16.h>
#include <math.h>

#define NB   8
#define ND   768
#define NCH  3
#define NMIX 5
#define H    10
#define NS   10
#define PI2f 6.283185307179586f
#define ZITTERf 1e-4f
#define INV_TEMP 10.0f
#define LOG2E 1.44269504088896341f

#define NJC 16              // j-chunks in feat
#define JC  48              // ND/NJC
#define ITILE 256           // i-range per feat block (2 i per thread)
#define NI_T  3             // ND/ITILE
#define FEAT_BLOCKS (NB * NCH * NI_T * NJC)   // 1152
#define NT2   6             // feat2 i-tiles of 128
#define FEAT2_BLOCKS (NB * NCH * NT2)          // 144
#define BUILD_BLOCKS 372                       // 372*128 = 47616 entries

#define OJT 128             // j-tile in out kernel (x3 channels = 384 threads)
#define OIT 64              // i-tile in out kernel (ND/OIT = 12)
#define OUT_BLOCKS (NB * (ND / OJT) * (ND / OIT))   // 576

#define TBLP   1984         // half2 pair-entries per (b,c); 3*TBLP*4 = 23808B shared
#define TSCALE 220.0f       // entries per unit |d| (covers |d| <= 9.0)
#define TCLAMP 1982.0f

// cross-kernel scratch (__device__ globals per allocation rules)
__device__ float g_facc[NB * NCH][NJC][NMIX][ND];   // feat partials, coalesced in i
__device__ float g_hpart[NB * NCH][NT2][H];
__device__ float g_w[NB * NCH * NMIX];
__device__ float g_diag[NCH];
__device__ __align__(16) __half2 g_ftab2[NB * NCH][TBLP];
__device__ int g_c0;    // feat main-work completions (target 1152)
__device__ int g_c1;    // feat2 completions (target 144)
__device__ int g_flag;  // weights ready

__device__ __forceinline__ float ex2f_(float x) {
    float y; asm("ex2.approx.f32 %0, %1;" : "=f"(y) : "f"(x)); return y;
}

// ---------------------------------------------------------------------------
// Kernel 1: feat main (all 1152 blocks) -> tail phases on low-indexed blocks:
//   blocks 0..143  : feat2 (layer-1 + i-reduction) after all main work done
//   block  0       : MLP layers 2-5 + Gumbel weights + diag
//   blocks 0..371  : build the half2 pair-packed lookup tables (128 ent each)
// All spinner blocks (0..371) are first-wave resident (1152 <= 1184 slots at
// __launch_bounds__(128,8)) -> no deadlock. Sync words reset by out_kernel.
// ---------------------------------------------------------------------------
__global__ void __launch_bounds__(128, 8) feat_kernel(
    const float* __restrict__ xc, const float* __restrict__ yc,
    const float* __restrict__ mu, const float* __restrict__ inv_std,
    const float* __restrict__ W1, const float* __restrict__ b1,
    const float* __restrict__ likerr, const float* __restrict__ unif,
    const float* __restrict__ W2, const float* __restrict__ b2,
    const float* __restrict__ W3, const float* __restrict__ b3,
    const float* __restrict__ W4, const float* __restrict__ b4,
    const float* __restrict__ W5, const float* __restrict__ b5)
{
    int bid = blockIdx.x;
    int tid = threadIdx.x;

    __shared__ float4 jt[JC][3];                 // 2304 B (feat main)
    __shared__ float sh2[128 * H];               // 5120 B (feat2 reduction)
    __shared__ float sh_h0[NB][NCH * H];         // MLP scratch
    __shared__ float sh_a[NB][H];
    __shared__ float sh_b[NB][H];
    __shared__ float sh_ll[NB][NCH * NMIX];
    __shared__ float sh_sm[NB][NS][NCH][NMIX];

    // ================= main pairwise reduction =================
    {
        int chunk = bid % NJC;
        int r     = bid / NJC;
        int tile  = r % NI_T;
        int bc    = r / NI_T;
        int c     = bc % NCH;
        int b     = bc / NCH;

        float km2[NMIX], pm[NMIX];
#pragma unroll
        for (int m = 0; m < NMIX; m++) {
            float iv = inv_std[m];
            km2[m] = -0.5f * PI2f * PI2f * iv * iv * LOG2E;
            pm[m]  = PI2f * mu[m];
        }

        int j0 = chunk * JC;
        if (tid < JC) {
            float xv = xc[(b * ND + j0 + tid) * NCH + c];
            float yv = yc[(b * ND + j0 + tid) * NCH + c];
            float cy[NMIX], sy[NMIX];
#pragma unroll
            for (int m = 0; m < NMIX; m++) {
                float s, co;
                __sincosf(pm[m] * xv, &s, &co);
                cy[m] = co * yv;
                sy[m] = s * yv;
            }
            jt[tid][0] = make_float4(cy[0], cy[1], cy[2], cy[3]);
            jt[tid][1] = make_float4(cy[4], sy[0], sy[1], sy[2]);
            jt[tid][2] = make_float4(sy[3], sy[4], xv, 0.f);
        }

        int i0 = tile * ITILE + tid;
        int i1 = i0 + 128;
        float xi0 = xc[(b * ND + i0) * NCH + c];
        float xi1 = xc[(b * ND + i1) * NCH + c];

        float A0[NMIX], B0[NMIX], A1[NMIX], B1[NMIX];
#pragma unroll
        for (int m = 0; m < NMIX; m++) { A0[m] = B0[m] = A1[m] = B1[m] = 0.f; }
        __syncthreads();

#pragma unroll 2
        for (int j = 0; j < JC; j++) {
            float4 t0 = jt[j][0];
            float4 t1 = jt[j][1];
            float4 t2 = jt[j][2];
            float cy[NMIX] = {t0.x, t0.y, t0.z, t0.w, t1.x};
            float sy[NMIX] = {t1.y, t1.z, t1.w, t2.x, t2.y};
            float xj = t2.z;
            float d0 = xi0 - xj, d20 = d0 * d0;
            float d1 = xi1 - xj, d21 = d1 * d1;
#pragma unroll
            for (int m = 0; m < NMIX; m++) {
                float e0 = ex2f_(km2[m] * d20);
                float e1 = ex2f_(km2[m] * d21);
                A0[m] = fmaf(e0, cy[m], A0[m]);
                B0[m] = fmaf(e0, sy[m], B0[m]);
                A1[m] = fmaf(e1, cy[m], A1[m]);
                B1[m] = fmaf(e1, sy[m], B1[m]);
            }
        }

#pragma unroll
        for (int m = 0; m < NMIX; m++) {
            float s0, c0, s1, c1;
            __sincosf(pm[m] * xi0, &s0, &c0);
            __sincosf(pm[m] * xi1, &s1, &c1);
            g_facc[bc][chunk][m][i0] = fmaf(c0, A0[m], s0 * B0[m]);
            g_facc[bc][chunk][m][i1] = fmaf(c1, A1[m], s1 * B1[m]);
        }
    }
    __syncthreads();
    if (tid == 0) { __threadfence(); atomicAdd(&g_c0, 1); }

    if (bid >= BUILD_BLOCKS) return;   // high blocks exit, freeing slots

    // ================= phase A: feat2 on blocks 0..143 =================
    if (bid < FEAT2_BLOCKS) {
        if (tid == 0) {
            while (atomicAdd(&g_c0, 0) < FEAT_BLOCKS) { __nanosleep(64); }
            __threadfence();
        }
        __syncthreads();

        int tile = bid % NT2;
        int bc   = bid / NT2;
        int c    = bc % NCH;
        int b    = bc / NCH;
        int i    = tile * 128 + tid;

        float yi = yc[(b * ND + i) * NCH + c];
        float tif[NMIX + 1];
#pragma unroll
        for (int m = 0; m < NMIX; m++) {
            float s = 0.f;
#pragma unroll
            for (int ch = 0; ch < NJC; ch++) s += g_facc[bc][ch][m][i];
            tif[m] = s + ZITTERf * yi;
        }
        tif[NMIX] = yi;

#pragma unroll
        for (int k = 0; k < H; k++) {
            float s = b1[k];
#pragma unroll
            for (int t = 0; t < NMIX + 1; t++) s = fmaf(W1[k * (NMIX + 1) + t], tif[t], s);
            sh2[tid * H + k] = fmaxf(s, 0.f);
        }
        __syncthreads();

        if (tid < H) {
            float s = 0.f;
            for (int t = 0; t < 128; t++) s += sh2[t * H + tid];
            g_hpart[bc][tile][tid] = s;
        }
        __syncthreads();
        if (tid == 0) { __threadfence(); atomicAdd(&g_c1, 1); }
    }

    // ================= phase B: block 0 runs the MLP =================
    if (bid == 0) {
        if (tid == 0) {
            while (atomicAdd(&g_c1, 0) < FEAT2_BLOCKS) { __nanosleep(64); }
            __threadfence();
        }
        __syncthreads();

        if (tid < NB * NCH) {
            int b = tid / NCH, c = tid % NCH;
            for (int k = 0; k < H; k++) {
                float s = 0.f;
#pragma unroll
                for (int tt = 0; tt < NT2; tt++) s += g_hpart[b * NCH + c][tt][k];
                sh_h0[b][c * H + k] = s * (1.0f / ND);
            }
        }
        if (tid < NCH) {
            float l = fminf(fmaxf(likerr[tid], 0.1f), 1.0f);
            g_diag[tid] = ZITTERf + l * l;
        }
        __syncthreads();

        if (tid < NB * H) {                       // layer 2
            int b = tid / H, k = tid % H;
            float s = b2[k];
            for (int u = 0; u < NCH * H; u++) s = fmaf(W2[k * (NCH * H) + u], sh_h0[b][u], s);
            sh_a[b][k] = fmaxf(s, 0.f);
        }
        __syncthreads();
        if (tid < NB * H) {                       // layer 3
            int b = tid / H, k = tid % H;
            float s = b3[k];
            for (int u = 0; u < H; u++) s = fmaf(W3[k * H + u], sh_a[b][u], s);
            sh_b[b][k] = fmaxf(s, 0.f);
        }
        __syncthreads();
        if (tid < NB * H) {                       // layer 4
            int b = tid / H, k = tid % H;
            float s = b4[k];
            for (int u = 0; u < H; u++) s = fmaf(W4[k * H + u], sh_b[b][u], s);
            sh_a[b][k] = fmaxf(s, 0.f);
        }
        __syncthreads();
        if (tid < NB * NCH * NMIX) {              // layer 5 -> logits
            int b = tid / (NCH * NMIX), n = tid % (NCH * NMIX);
            float s = b5[n];
            for (int u = 0; u < H; u++) s = fmaf(W5[n * H + u], sh_a[b][u], s);
            sh_ll[b][n] = s;
        }
        __syncthreads();

        for (int t = tid; t < NB * NS * NCH; t += 128) {   // gumbel softmax
            int b = t / (NS * NCH);
            int rem = t % (NS * NCH);
            int s = rem / NCH, c = rem % NCH;
            float z[NMIX], mx = -1e30f;
#pragma unroll
            for (int m = 0; m < NMIX; m++) {
                float u = unif[((b * NS + s) * NCH + c) * NMIX + m];
                float g = -__logf(-__logf(u + 1e-20f));
                z[m] = (g + sh_ll[b][c * NMIX + m]) * INV_TEMP;
                mx = fmaxf(mx, z[m]);
            }
            float sum = 0.f, e[NMIX];
#pragma unroll
            for (int m = 0; m < NMIX; m++) { e[m] = __expf(z[m] - mx); sum += e[m]; }
            float inv = 1.f / sum;
#pragma unroll
            for (int m = 0; m < NMIX; m++) sh_sm[b][s][c][m] = e[m] * inv;
        }
        __syncthreads();

        if (tid < NB * NCH * NMIX) {              // mean over samples
            int b = tid / (NCH * NMIX);
            int cm = tid % (NCH * NMIX);
            int c = cm / NMIX, m = cm % NMIX;
            float s = 0.f;
#pragma unroll
            for (int ss = 0; ss < NS; ss++) s += sh_sm[b][ss][c][m];
            g_w[(b * NCH + c) * NMIX + m] = s * (1.0f / NS);
        }
        __syncthreads();
        if (tid == 0) { __threadfence(); atomicExch(&g_flag, 1); }
    }

    // ============ phase C: blocks 0..371 build table entries ============
    if (tid == 0) {
        while (atomicAdd(&g_flag, 0) == 0) { __nanosleep(64); }
        __threadfence();
    }
    __syncthreads();

    {
        int idx = bid * 128 + tid;                // 372*128 = 47616 = 24*1984
        int bc  = idx / TBLP;
        int k   = idx % TBLP;
        float d0 = (float)k * (1.0f / TSCALE);
        float d1 = (float)(k + 1) * (1.0f / TSCALE);
        float d20 = d0 * d0, d21 = d1 * d1;
        float a0 = 0.f, a1 = 0.f;
#pragma unroll
        for (int m = 0; m < NMIX; m++) {
            float iv = inv_std[m];
            float a  = -0.5f * PI2f * PI2f * iv * iv * LOG2E;
            float p  = PI2f * mu[m];
            float w  = g_w[bc * NMIX + m];
            a0 = fmaf(w, ex2f_(a * d20) * __cosf(p * d0), a0);
            a1 = fmaf(w, ex2f_(a * d21) * __cosf(p * d1), a1);
        }
        g_ftab2[bc][k] = __floats2half2_rn(a0, a1);
    }
}

// ---------------------------------------------------------------------------
// Kernel 2: pure LUT output, channel-parallel mapping.
// 384 threads = 128 j x 3 c; warp stores are contiguous 128B (1 wavefront).
// block = (b, j-tile 128, i-tile 64); per element 1 LDS.32 + lerp + 1 STG.32.
// Resets feat sync words (runs last).
// ---------------------------------------------------------------------------
__global__ void __launch_bounds__(384) out_kernel(
    const float* __restrict__ xc, float* __restrict__ out)
{
    int blk = blockIdx.x;
    int tid = threadIdx.x;

    __shared__ __half2 fs2[NCH * TBLP];   // 23808 B
    __shared__ float xish[OIT * NCH];

    int itile = blk % (ND / OIT);
    int rr_   = blk / (ND / OIT);
    int jt    = rr_ % (ND / OJT);
    int ob    = rr_ / (ND / OJT);
    int ibase = itile * OIT;

    int jloc = tid / NCH;          // 0..127
    int c    = tid - jloc * NCH;   // 0..2
    int j    = jt * OJT + jloc;
    float xj = xc[((size_t)ob * ND + j) * NCH + c];
    float dg = g_diag[c];
    if (tid < OIT * NCH)
        xish[tid] = xc[((size_t)ob * ND + ibase) * NCH + tid];

    {
        const float4* src = (const float4*)&g_ftab2[ob * NCH][0];
        float4* dst = (float4*)fs2;
        for (int q = tid; q < NCH * TBLP / 4; q += 384) dst[q] = src[q];
    }
    __syncthreads();

    const __half2* tab = &fs2[c * TBLP];
    // contiguous store index: addr = (i*ND + jt*OJT)*NCH + tid
    float* o = out + (((size_t)ob * ND + ibase) * ND + jt * OJT) * NCH + tid;

#pragma unroll 1
    for (int ii = 0; ii < OIT; ii += 2) {
        int iA = ibase + ii;
        int iB = iA + 1;
        float tA = fminf(fabsf(xish[ii * NCH + c] - xj) * TSCALE, TCLAMP);
        float tB = fminf(fabsf(xish[ii * NCH + NCH + c] - xj) * TSCALE, TCLAMP);
        int kA = (int)tA, kB = (int)tB;
        float2 pA = __half22float2(tab[kA]);
        float2 pB = __half22float2(tab[kB]);
        float fA = tA - (float)kA, fB = tB - (float)kB;
        float rA = fmaf(fA, pA.y - pA.x, pA.x);
        float rB = fmaf(fB, pB.y - pB.x, pB.x);
        if (iA == j) rA += dg;
        if (iB == j) rB += dg;
        o[0] = rA;
        o += (size_t)ND * NCH;
        o[0] = rB;
        o += (size_t)ND * NCH;
    }

    // reset sync words for the next graph replay (kernel boundary publishes)
    if (blk == 0 && tid == 0) { g_c0 = 0; g_c1 = 0; g_flag = 0; }
}

extern "C" void kernel_launch(void* const* d_in, const int* in_sizes, int n_in,
                              void* d_out, int out_size)
{
    const float* xc      = (const float*)d_in[0];
    const float* yc      = (const float*)d_in[1];
    const float* mu      = (const float*)d_in[2];
    const float* inv_std = (const float*)d_in[3];
    const float* likerr  = (const float*)d_in[4];
    const float* unif    = (const float*)d_in[5];
    const float* W1 = (const float*)d_in[6];  const float* b1 = (const float*)d_in[7];
    const float* W2 = (const float*)d_in[8];  const float* b2 = (const float*)d_in[9];
    const float* W3 = (const float*)d_in[10]; const float* b3 = (const float*)d_in[11];
    const float* W4 = (const float*)d_in[12]; const float* b4 = (const float*)d_in[13];
    const float* W5 = (const float*)d_in[14]; const float* b5 = (const float*)d_in[15];

    feat_kernel<<<FEAT_BLOCKS, 128>>>(xc, yc, mu, inv_std, W1, b1, likerr, unif,
                                      W2, b2, W3, b3, W4, b4, W5, b5);
    out_kernel<<<OUT_BLOCKS, 384>>>(xc, (float*)d_out);
}